// round 12
// baseline (speedup 1.0000x reference)
#include <cuda_runtime.h>

#define BB 64
#define TT 577
#define DD 768
#define DENS 519      // int(577*0.9)
#define NSKIP 58      // 577 - 519
#define D4 (DD/4)     // 192 float4 per row
#define RPB 8         // source rows per scatter block
#define NROWS (BB*TT) // 36928
#define NSCAT (NROWS/RPB) // 4616

// Scratch (no device allocation allowed)
__device__ float g_logits[NROWS];
__device__ int   g_rank[NROWS];
__device__ int   g_skip[BB*NSKIP];
__device__ float g_weights[BB*NSKIP];

__device__ __forceinline__ void pdl_trigger() {
    asm volatile("griddepcontrol.launch_dependents;");
}
__device__ __forceinline__ void pdl_wait() {
    asm volatile("griddepcontrol.wait;" ::: "memory");
}

// ---------------- Kernel 1: logits = x @ w + b  (one warp per TWO rows) ----------------
// Verified 21us @ ~68% DRAM — body unchanged; PDL trigger at end.
__global__ void logits_kernel(const float* __restrict__ x,
                              const float* __restrict__ w,
                              const float* __restrict__ bias) {
    int warpsPerBlock = blockDim.x >> 5;
    int warpId = threadIdx.x >> 5;
    int lane   = threadIdx.x & 31;
    int pair = blockIdx.x * warpsPerBlock + warpId;
    int row0 = pair * 2;
    if (row0 < NROWS) {
        const float4* xr0 = reinterpret_cast<const float4*>(x) + (size_t)row0 * D4;
        const float4* xr1 = xr0 + D4;
        const float4* w4  = reinterpret_cast<const float4*>(w);

        float4 a0[6], a1[6], wv[6];
        #pragma unroll
        for (int k = 0; k < 6; k++) a0[k] = xr0[k*32 + lane];
        #pragma unroll
        for (int k = 0; k < 6; k++) a1[k] = xr1[k*32 + lane];
        #pragma unroll
        for (int k = 0; k < 6; k++) wv[k] = __ldg(&w4[k*32 + lane]);

        float acc0 = 0.f, acc1 = 0.f;
        #pragma unroll
        for (int k = 0; k < 6; k++) {
            acc0 = fmaf(a0[k].x, wv[k].x, acc0);
            acc0 = fmaf(a0[k].y, wv[k].y, acc0);
            acc0 = fmaf(a0[k].z, wv[k].z, acc0);
            acc0 = fmaf(a0[k].w, wv[k].w, acc0);
            acc1 = fmaf(a1[k].x, wv[k].x, acc1);
            acc1 = fmaf(a1[k].y, wv[k].y, acc1);
            acc1 = fmaf(a1[k].z, wv[k].z, acc1);
            acc1 = fmaf(a1[k].w, wv[k].w, acc1);
        }
        #pragma unroll
        for (int off = 16; off; off >>= 1) {
            acc0 += __shfl_xor_sync(0xffffffffu, acc0, off);
            acc1 += __shfl_xor_sync(0xffffffffu, acc1, off);
        }
        if (lane == 0) {
            float bv = bias[0];
            g_logits[row0]     = acc0 + bv;
            g_logits[row0 + 1] = acc1 + bv;
        }
    }
    pdl_trigger();   // all logits stores done in this block -> allow rank launch
}

// ---------------- Kernel 2: rank (stable) + skip softmax ----------------
__global__ void rank_kernel() {
    __shared__ float s[TT];
    __shared__ float skipP[NSKIP];
    __shared__ float skipE[NSKIP];

    int b = blockIdx.x;
    int i = threadIdx.x;

    pdl_wait();      // logits kernel's writes visible after this

    if (i < TT) s[i] = g_logits[b*TT + i];
    __syncthreads();

    if (i < TT) {
        float my = s[i];
        int rank = 0;
        #pragma unroll 8
        for (int j = 0; j < TT; j++) {
            float v = s[j];
            rank += (v > my) || (v == my && j < i);   // stable: lower index wins
        }
        g_rank[b*TT + i] = rank;
        if (rank >= DENS) {
            int pos = (TT - 1) - rank;                // ascending skipped order
            g_skip[b*NSKIP + pos] = i;
            skipP[pos] = 1.f / (1.f + expf(-my));     // sigmoid prob
        }
    }
    __syncthreads();

    if (i < NSKIP) {
        float m = -1e30f;
        #pragma unroll
        for (int j = 0; j < NSKIP; j++) m = fmaxf(m, skipP[j]);
        skipE[i] = expf(skipP[i] - m);
    }
    __syncthreads();

    if (i < NSKIP) {
        float sum = 0.f;
        #pragma unroll
        for (int j = 0; j < NSKIP; j++) sum += skipE[j];
        g_weights[b*NSKIP + i] = skipE[i] / sum;
    }
    pdl_trigger();   // ranks + weights written -> allow scatter launch
}

// ---------------- Kernel 3: fused scatter + summary (PDL-overlapped) ----------------
// Scatter blocks: front-issue 8 streaming x loads BEFORE pdl_wait -> these reads
// stream on idle SMs while rank_kernel (64 blocks) runs. Then wait, load ranks, store.
__global__ void __launch_bounds__(192)
scatter_summary_kernel(const float* __restrict__ x, float* __restrict__ out) {
    const float4* xin = reinterpret_cast<const float4*>(x);
    float4* o4 = reinterpret_cast<float4*>(out);
    const size_t skipBase = (size_t)BB * DENS * D4;
    const size_t sumBase  = (size_t)BB * (DENS + NSKIP) * D4;
    int tid = threadIdx.x;              // 0..191

    if (blockIdx.x < BB) {
        // ---- summary: needs skip/weights -> wait first ----
        __shared__ int   sidx[64];
        __shared__ float swgt[64];
        int b = blockIdx.x;
        pdl_wait();
        if (tid < 64) {
            sidx[tid] = (tid < NSKIP) ? g_skip[b*NSKIP + tid] : 0;
            swgt[tid] = (tid < NSKIP) ? g_weights[b*NSKIP + tid] : 0.f;
        }
        __syncthreads();

        float4 acc = make_float4(0.f, 0.f, 0.f, 0.f);
        #pragma unroll
        for (int g = 0; g < 64; g += 8) {
            float4 vv[8];
            #pragma unroll
            for (int j = 0; j < 8; j++)
                vv[j] = xin[((size_t)b*TT + sidx[g+j]) * D4 + tid];
            #pragma unroll
            for (int j = 0; j < 8; j++) {
                float wgt = swgt[g+j];
                acc.x = fmaf(wgt, vv[j].x, acc.x);
                acc.y = fmaf(wgt, vv[j].y, acc.y);
                acc.z = fmaf(wgt, vv[j].z, acc.z);
                acc.w = fmaf(wgt, vv[j].w, acc.w);
            }
        }
        o4[sumBase + (size_t)b * D4 + tid] = acc;
    } else {
        // ---- scatter: x loads FIRST (rank-independent, overlap rank kernel) ----
        int sb = (NSCAT - 1) - ((int)blockIdx.x - BB);  // reversed: freshest L2 lines first
        int base = sb * RPB;

        float4 v[RPB];
        #pragma unroll
        for (int r = 0; r < RPB; r++)
            v[r] = __ldcs(&xin[((size_t)(base + r)) * D4 + tid]);

        pdl_wait();       // ranks now final + visible

        int rk[RPB];
        #pragma unroll
        for (int r = 0; r < RPB; r++) rk[r] = g_rank[base + r];

        #pragma unroll
        for (int r = 0; r < RPB; r++) {
            int b = (base + r) / TT;
            int rank = rk[r];
            size_t off = (rank < DENS)
                ? ((size_t)(b*DENS + rank) * D4)
                : (skipBase + (size_t)(b*NSKIP + ((TT-1) - rank)) * D4);
            __stcs(&o4[off + tid], v[r]);
        }
    }
}

extern "C" void kernel_launch(void* const* d_in, const int* in_sizes, int n_in,
                              void* d_out, int out_size) {
    const float* x    = (const float*)d_in[0];
    const float* w    = (const float*)d_in[1];
    const float* bias = (const float*)d_in[2];
    float* out = (float*)d_out;

    // 1) logits (normal launch)
    logits_kernel<<<(NROWS/2 + 7) / 8, 256>>>(x, w, bias);

    // 2) rank + softmax — programmatic launch (overlaps k1 tail)
    {
        cudaLaunchConfig_t cfg = {};
        cfg.gridDim = dim3(BB);
        cfg.blockDim = dim3(608);
        cudaLaunchAttribute attr[1];
        attr[0].id = cudaLaunchAttributeProgrammaticStreamSerialization;
        attr[0].val.programmaticStreamSerializationAllowed = 1;
        cfg.attrs = attr;
        cfg.numAttrs = 1;
        cudaLaunchKernelEx(&cfg, rank_kernel);
    }

    // 3) scatter + summary — programmatic launch (x loads overlap rank kernel)
    {
        cudaLaunchConfig_t cfg = {};
        cfg.gridDim = dim3(BB + NSCAT);
        cfg.blockDim = dim3(192);
        cudaLaunchAttribute attr[1];
        attr[0].id = cudaLaunchAttributeProgrammaticStreamSerialization;
        attr[0].val.programmaticStreamSerializationAllowed = 1;
        cfg.attrs = attr;
        cfg.numAttrs = 1;
        cudaLaunchKernelEx(&cfg, scatter_summary_kernel, x, out);
    }
}

// round 13
// speedup vs baseline: 1.0927x; 1.0927x over previous
#include <cuda_runtime.h>

#define BB 64
#define TT 577
#define DD 768
#define DENS 519      // int(577*0.9)
#define NSKIP 58      // 577 - 519
#define D4 (DD/4)     // 192 float4 per row
#define RPB 8         // source rows per scatter block
#define NROWS (BB*TT) // 36928
#define NSCAT (NROWS/RPB) // 4616

// Scratch (no device allocation allowed)
__device__ float g_logits[NROWS];

// ---------------- Kernel 1: logits = x @ w + b  (one warp per TWO rows) ----------------
// Verified ~21us @ ~70% DRAM — unchanged.
__global__ void logits_kernel(const float* __restrict__ x,
                              const float* __restrict__ w,
                              const float* __restrict__ bias) {
    int warpsPerBlock = blockDim.x >> 5;
    int warpId = threadIdx.x >> 5;
    int lane   = threadIdx.x & 31;
    int pair = blockIdx.x * warpsPerBlock + warpId;
    int row0 = pair * 2;
    if (row0 >= NROWS) return;

    const float4* xr0 = reinterpret_cast<const float4*>(x) + (size_t)row0 * D4;
    const float4* xr1 = xr0 + D4;
    const float4* w4  = reinterpret_cast<const float4*>(w);

    float4 a0[6], a1[6], wv[6];
    #pragma unroll
    for (int k = 0; k < 6; k++) a0[k] = xr0[k*32 + lane];
    #pragma unroll
    for (int k = 0; k < 6; k++) a1[k] = xr1[k*32 + lane];
    #pragma unroll
    for (int k = 0; k < 6; k++) wv[k] = __ldg(&w4[k*32 + lane]);

    float acc0 = 0.f, acc1 = 0.f;
    #pragma unroll
    for (int k = 0; k < 6; k++) {
        acc0 = fmaf(a0[k].x, wv[k].x, acc0);
        acc0 = fmaf(a0[k].y, wv[k].y, acc0);
        acc0 = fmaf(a0[k].z, wv[k].z, acc0);
        acc0 = fmaf(a0[k].w, wv[k].w, acc0);
        acc1 = fmaf(a1[k].x, wv[k].x, acc1);
        acc1 = fmaf(a1[k].y, wv[k].y, acc1);
        acc1 = fmaf(a1[k].z, wv[k].z, acc1);
        acc1 = fmaf(a1[k].w, wv[k].w, acc1);
    }
    #pragma unroll
    for (int off = 16; off; off >>= 1) {
        acc0 += __shfl_xor_sync(0xffffffffu, acc0, off);
        acc1 += __shfl_xor_sync(0xffffffffu, acc1, off);
    }
    if (lane == 0) {
        float bv = bias[0];
        g_logits[row0]     = acc0 + bv;
        g_logits[row0 + 1] = acc1 + bv;
    }
}

// ---------------- Kernel 2: scatter + summary with LOCAL rank recompute ----------------
// Blocks [0, BB)        : rank whole batch in-block + softmax + MLP-8 summary
// Blocks [BB, BB+NSCAT) : rank own 8 rows in-block (1 warp/row), then scatter
__global__ void __launch_bounds__(256)
scatter_summary_kernel(const float* __restrict__ x, float* __restrict__ out) {
    __shared__ float slog[2*TT];         // logits of up to 2 batches
    const float4* xin = reinterpret_cast<const float4*>(x);
    float4* o4 = reinterpret_cast<float4*>(out);
    const size_t skipBase = (size_t)BB * DENS * D4;
    const size_t sumBase  = (size_t)BB * (DENS + NSKIP) * D4;
    int tid  = threadIdx.x;
    int wrp  = tid >> 5;
    int lane = tid & 31;

    if (blockIdx.x < BB) {
        // ======== summary for batch b: rank all rows locally ========
        __shared__ int   sidx[64];       // padded
        __shared__ float swgt[64];       // padded
        __shared__ float skipP[NSKIP];
        __shared__ float skipE[NSKIP];
        int b = blockIdx.x;

        for (int i = tid; i < TT; i += 256) slog[i] = g_logits[b*TT + i];
        if (tid < 64) { sidx[tid] = 0; swgt[tid] = 0.f; }
        __syncthreads();

        // one warp per row, lane-strided count, shfl reduce
        for (int i = wrp; i < TT; i += 8) {
            float my = slog[i];
            int cnt = 0;
            for (int j = lane; j < TT; j += 32) {
                float v = slog[j];
                cnt += (v > my) || (v == my && j < i);   // stable
            }
            #pragma unroll
            for (int off = 16; off; off >>= 1)
                cnt += __shfl_xor_sync(0xffffffffu, cnt, off);
            if (lane == 0 && cnt >= DENS) {
                int pos = (TT - 1) - cnt;                // ascending skipped order
                sidx[pos] = i;
                skipP[pos] = 1.f / (1.f + expf(-my));    // sigmoid prob
            }
        }
        __syncthreads();

        if (tid < NSKIP) {
            float m = -1e30f;
            #pragma unroll
            for (int j = 0; j < NSKIP; j++) m = fmaxf(m, skipP[j]);
            skipE[tid] = expf(skipP[tid] - m);
        }
        __syncthreads();
        if (tid < NSKIP) {
            float sum = 0.f;
            #pragma unroll
            for (int j = 0; j < NSKIP; j++) sum += skipE[j];
            swgt[tid] = skipE[tid] / sum;
        }
        __syncthreads();

        if (tid < 192) {
            float4 acc = make_float4(0.f, 0.f, 0.f, 0.f);
            #pragma unroll
            for (int g = 0; g < 64; g += 8) {
                float4 vv[8];
                #pragma unroll
                for (int j = 0; j < 8; j++)
                    vv[j] = xin[((size_t)b*TT + sidx[g+j]) * D4 + tid];
                #pragma unroll
                for (int j = 0; j < 8; j++) {
                    float wgt = swgt[g+j];
                    acc.x = fmaf(wgt, vv[j].x, acc.x);
                    acc.y = fmaf(wgt, vv[j].y, acc.y);
                    acc.z = fmaf(wgt, vv[j].z, acc.z);
                    acc.w = fmaf(wgt, vv[j].w, acc.w);
                }
            }
            o4[sumBase + (size_t)b * D4 + tid] = acc;
        }
    } else {
        // ======== scatter: front-issue x loads, rank 8 rows locally, store ========
        __shared__ int sRank[RPB];
        int sb = (NSCAT - 1) - ((int)blockIdx.x - BB);  // reversed traversal
        int base = sb * RPB;
        int b0 = base / TT;
        int b1 = (base + RPB - 1) / TT;                 // at most b0+1

        // 1) front-batched streaming x loads (192 float4 lanes, MLP=8)
        float4 v[RPB];
        if (tid < 192) {
            #pragma unroll
            for (int r = 0; r < RPB; r++)
                v[r] = __ldcs(&xin[((size_t)(base + r)) * D4 + tid]);
        }

        // 2) load batch logits into smem (L2-hot, broadcast across blocks)
        for (int i = tid; i < TT; i += 256) slog[i] = g_logits[b0*TT + i];
        if (b1 != b0)
            for (int i = tid; i < TT; i += 256) slog[TT + i] = g_logits[b1*TT + i];
        __syncthreads();

        // 3) rank: one warp per row (overlapped with in-flight x loads)
        if (wrp < RPB) {
            int src = base + wrp;
            int b = src / TT;
            int i = src - b*TT;
            const float* lg = slog + ((b == b0) ? 0 : TT);
            float my = lg[i];
            int cnt = 0;
            for (int j = lane; j < TT; j += 32) {
                float vv = lg[j];
                cnt += (vv > my) || (vv == my && j < i); // stable
            }
            #pragma unroll
            for (int off = 16; off; off >>= 1)
                cnt += __shfl_xor_sync(0xffffffffu, cnt, off);
            if (lane == 0) sRank[wrp] = cnt;
        }
        __syncthreads();

        // 4) stores
        if (tid < 192) {
            #pragma unroll
            for (int r = 0; r < RPB; r++) {
                int b = (base + r) / TT;
                int rank = sRank[r];
                size_t off = (rank < DENS)
                    ? ((size_t)(b*DENS + rank) * D4)
                    : (skipBase + (size_t)(b*NSKIP + ((TT-1) - rank)) * D4);
                __stcs(&o4[off + tid], v[r]);
            }
        }
    }
}

extern "C" void kernel_launch(void* const* d_in, const int* in_sizes, int n_in,
                              void* d_out, int out_size) {
    const float* x    = (const float*)d_in[0];
    const float* w    = (const float*)d_in[1];
    const float* bias = (const float*)d_in[2];
    float* out = (float*)d_out;

    // 1) logits: 2 rows/warp, 8 warps/block (verified)
    logits_kernel<<<(NROWS/2 + 7) / 8, 256>>>(x, w, bias);
    // 2) scatter + summaries with local rank recompute (no rank kernel)
    scatter_summary_kernel<<<BB + NSCAT, 256>>>(x, out);
}

// round 14
// speedup vs baseline: 1.1281x; 1.0324x over previous
#include <cuda_runtime.h>

#define BB 64
#define TT 577
#define DD 768
#define DENS 519      // int(577*0.9)
#define NSKIP 58      // 577 - 519
#define D4 (DD/4)     // 192 float4 per row
#define RPB 8         // source rows per scatter block
#define NROWS (BB*TT) // 36928
#define NSCAT (NROWS/RPB) // 4616

// Scratch (no device allocation allowed)
__device__ float g_logits[NROWS];
__device__ int   g_rank[NROWS];
__device__ int   g_skip[BB*NSKIP];
__device__ float g_weights[BB*NSKIP];

// ---------------- Kernel 1: logits = x @ w + b  (one warp per TWO rows) ----------------
// Verified ~21us @ ~70% DRAM — unchanged.
__global__ void logits_kernel(const float* __restrict__ x,
                              const float* __restrict__ w,
                              const float* __restrict__ bias) {
    int warpsPerBlock = blockDim.x >> 5;
    int warpId = threadIdx.x >> 5;
    int lane   = threadIdx.x & 31;
    int pair = blockIdx.x * warpsPerBlock + warpId;
    int row0 = pair * 2;
    if (row0 >= NROWS) return;

    const float4* xr0 = reinterpret_cast<const float4*>(x) + (size_t)row0 * D4;
    const float4* xr1 = xr0 + D4;
    const float4* w4  = reinterpret_cast<const float4*>(w);

    float4 a0[6], a1[6], wv[6];
    #pragma unroll
    for (int k = 0; k < 6; k++) a0[k] = xr0[k*32 + lane];
    #pragma unroll
    for (int k = 0; k < 6; k++) a1[k] = xr1[k*32 + lane];
    #pragma unroll
    for (int k = 0; k < 6; k++) wv[k] = __ldg(&w4[k*32 + lane]);

    float acc0 = 0.f, acc1 = 0.f;
    #pragma unroll
    for (int k = 0; k < 6; k++) {
        acc0 = fmaf(a0[k].x, wv[k].x, acc0);
        acc0 = fmaf(a0[k].y, wv[k].y, acc0);
        acc0 = fmaf(a0[k].z, wv[k].z, acc0);
        acc0 = fmaf(a0[k].w, wv[k].w, acc0);
        acc1 = fmaf(a1[k].x, wv[k].x, acc1);
        acc1 = fmaf(a1[k].y, wv[k].y, acc1);
        acc1 = fmaf(a1[k].z, wv[k].z, acc1);
        acc1 = fmaf(a1[k].w, wv[k].w, acc1);
    }
    #pragma unroll
    for (int off = 16; off; off >>= 1) {
        acc0 += __shfl_xor_sync(0xffffffffu, acc0, off);
        acc1 += __shfl_xor_sync(0xffffffffu, acc1, off);
    }
    if (lane == 0) {
        float bv = bias[0];
        g_logits[row0]     = acc0 + bv;
        g_logits[row0 + 1] = acc1 + bv;
    }
}

// ---------------- Kernel 2: rank (stable) + skip softmax ----------------
__global__ void rank_kernel() {
    __shared__ float s[TT];
    __shared__ float skipP[NSKIP];
    __shared__ float skipE[NSKIP];

    int b = blockIdx.x;
    int i = threadIdx.x;

    if (i < TT) s[i] = g_logits[b*TT + i];
    __syncthreads();

    if (i < TT) {
        float my = s[i];
        int rank = 0;
        #pragma unroll 8
        for (int j = 0; j < TT; j++) {
            float v = s[j];
            rank += (v > my) || (v == my && j < i);   // stable: lower index wins
        }
        g_rank[b*TT + i] = rank;
        if (rank >= DENS) {
            int pos = (TT - 1) - rank;                // ascending skipped order
            g_skip[b*NSKIP + pos] = i;
            skipP[pos] = 1.f / (1.f + expf(-my));     // sigmoid prob
        }
    }
    __syncthreads();

    if (i < NSKIP) {
        float m = -1e30f;
        #pragma unroll
        for (int j = 0; j < NSKIP; j++) m = fmaxf(m, skipP[j]);
        skipE[i] = expf(skipP[i] - m);
    }
    __syncthreads();

    if (i < NSKIP) {
        float sum = 0.f;
        #pragma unroll
        for (int j = 0; j < NSKIP; j++) sum += skipE[j];
        g_weights[b*NSKIP + i] = skipE[i] / sum;
    }
}

// ---------------- Kernel 3: fused scatter + summary (reg-trimmed) ----------------
// Blocks [0, BB)        : MLP-8 summary for batch blockIdx.x (hidden under scatter stream)
// Blocks [BB, BB+NSCAT) : scatter RPB sequential rows, reversed traversal.
//                         Store offsets precomputed as 32-bit float4 indices.
__global__ void __launch_bounds__(192)
scatter_summary_kernel(const float* __restrict__ x, float* __restrict__ out) {
    const float4* xin = reinterpret_cast<const float4*>(x);
    float4* o4 = reinterpret_cast<float4*>(out);
    const unsigned skipBase = (unsigned)(BB * DENS) * D4;        // float4 units, < 2^31
    const unsigned sumBase  = (unsigned)(BB * (DENS + NSKIP)) * D4;
    int tid = threadIdx.x;              // 0..191

    if (blockIdx.x < BB) {
        // ---- summary: 8 groups of 8 front-batched loads (padded to 64, weight 0) ----
        __shared__ int   sidx[64];
        __shared__ float swgt[64];
        int b = blockIdx.x;
        if (tid < 64) {
            sidx[tid] = (tid < NSKIP) ? g_skip[b*NSKIP + tid] : 0;
            swgt[tid] = (tid < NSKIP) ? g_weights[b*NSKIP + tid] : 0.f;
        }
        __syncthreads();

        float4 acc = make_float4(0.f, 0.f, 0.f, 0.f);
        #pragma unroll
        for (int g = 0; g < 64; g += 8) {
            float4 vv[8];
            #pragma unroll
            for (int j = 0; j < 8; j++)
                vv[j] = xin[((size_t)(b*TT + sidx[g+j])) * D4 + tid];
            #pragma unroll
            for (int j = 0; j < 8; j++) {
                float wgt = swgt[g+j];
                acc.x = fmaf(wgt, vv[j].x, acc.x);
                acc.y = fmaf(wgt, vv[j].y, acc.y);
                acc.z = fmaf(wgt, vv[j].z, acc.z);
                acc.w = fmaf(wgt, vv[j].w, acc.w);
            }
        }
        o4[sumBase + (unsigned)b * D4 + tid] = acc;
    } else {
        // ---- scatter ----
        int sb = (NSCAT - 1) - ((int)blockIdx.x - BB);  // reversed: freshest L2 lines first
        int base = sb * RPB;
        int b0 = base / TT;                              // one division per block
        int t0 = base - b0 * TT;                         // row-in-batch of first row

        // Precompute 32-bit store offsets (frees rank/size_t registers before loads)
        unsigned off4[RPB];
        #pragma unroll
        for (int r = 0; r < RPB; r++) {
            int b = b0 + ((t0 + r) >= TT);               // span crosses <= 1 batch edge
            int rank = __ldg(&g_rank[base + r]);
            off4[r] = (rank < DENS)
                ? ((unsigned)(b*DENS + rank) * D4 + tid)
                : (skipBase + (unsigned)(b*NSKIP + ((TT-1) - rank)) * D4 + tid);
        }

        // Front-batched independent streaming loads (MLP=8)
        float4 v[RPB];
        #pragma unroll
        for (int r = 0; r < RPB; r++)
            v[r] = __ldcs(&xin[((size_t)(base + r)) * D4 + tid]);

        #pragma unroll
        for (int r = 0; r < RPB; r++)
            __stcs(&o4[off4[r]], v[r]);
    }
}

extern "C" void kernel_launch(void* const* d_in, const int* in_sizes, int n_in,
                              void* d_out, int out_size) {
    const float* x    = (const float*)d_in[0];
    const float* w    = (const float*)d_in[1];
    const float* bias = (const float*)d_in[2];
    float* out = (float*)d_out;

    // 1) logits: 2 rows/warp, 8 warps/block (verified ~21us)
    logits_kernel<<<(NROWS/2 + 7) / 8, 256>>>(x, w, bias);
    // 2) rank + softmax (one block per batch, ~2.5us)
    rank_kernel<<<BB, 608>>>();
    // 3) scatter + summaries (reg-trimmed)
    scatter_summary_kernel<<<BB + NSCAT, 192>>>(x, out);
}